// round 1
// baseline (speedup 1.0000x reference)
#include <cuda_runtime.h>

typedef unsigned long long u64;

#define NTHREADS 128
#define NBLOCKS  (148 * 3)

// ---------------- packed f32x2 helpers (sm_103a) ----------------
__device__ __forceinline__ u64 fma2(u64 a, u64 b, u64 c) {
    u64 d;
    asm("fma.rn.f32x2 %0, %1, %2, %3;" : "=l"(d) : "l"(a), "l"(b), "l"(c));
    return d;
}
__device__ __forceinline__ u64 pack2(float lo, float hi) {
    u64 d;
    asm("mov.b64 %0, {%1, %2};" : "=l"(d) : "f"(lo), "f"(hi));
    return d;
}
__device__ __forceinline__ void unpack2(u64 v, float& lo, float& hi) {
    asm("mov.b64 {%0, %1}, %2;" : "=f"(lo), "=f"(hi) : "l"(v));
}
__device__ __forceinline__ u64 bcast(float x) { return pack2(x, x); }
__device__ __forceinline__ u64 lds64(const float* p) {
    return *reinterpret_cast<const u64*>(p);
}

// ---------------- fast activations (accurate to ~1e-6 rel) ----------------
__device__ __forceinline__ float sigf(float x) {
    float e = __expf(-x);
    return __fdividef(1.0f, 1.0f + e);
}
__device__ __forceinline__ float tanhfast(float x) {
    float e = __expf(-2.0f * x);
    return __fdividef(2.0f, 1.0f + e) - 1.0f;
}

// SMEM layout (floats): offsets, all even (8B-aligned for LDS.64)
#define OFF_W2T   0        // 64*128 = 8192, layout [j][k]: (W2[k][j],W2[k+1][j]) contiguous
#define OFF_W1T   8192     // 20*128 = 2560, layout [i][j]: (W1[j][i],W1[j+1][i]) contiguous
#define OFF_W3T   10752    // 64*32  = 2048, layout [k][m]: (W3[m][k],W3[m+1][k]) contiguous
#define OFF_B1    12800    // 128
#define OFF_B2    12928    // 64
#define OFF_B3    12992    // 32
#define OFF_W4    13024    // 32
#define OFF_WIH   13056    // 32 (8x4, row-major as given)
#define OFF_WHH   13088    // 16 (8x2)
#define OFF_BIAS  13104    // 8  (b_ih + b_hh)
#define OFF_B4    13112    // 1
#define SMEM_FLOATS 13120
#define SMEM_BYTES  (SMEM_FLOATS * 4)

__global__ void __launch_bounds__(NTHREADS, 3)
lstm_mlp_fused_kernel(const float* __restrict__ x,
                      const float* __restrict__ W_ih, const float* __restrict__ W_hh,
                      const float* __restrict__ b_ih, const float* __restrict__ b_hh,
                      const float* __restrict__ W1, const float* __restrict__ b1,
                      const float* __restrict__ W2, const float* __restrict__ b2,
                      const float* __restrict__ W3, const float* __restrict__ b3,
                      const float* __restrict__ W4, const float* __restrict__ b4,
                      float* __restrict__ out, int n)
{
    extern __shared__ float sm[];
    float* sW2t  = sm + OFF_W2T;
    float* sW1t  = sm + OFF_W1T;
    float* sW3t  = sm + OFF_W3T;
    float* sB1   = sm + OFF_B1;
    float* sB2   = sm + OFF_B2;
    float* sB3   = sm + OFF_B3;
    float* sW4   = sm + OFF_W4;
    float* sWih  = sm + OFF_WIH;
    float* sWhh  = sm + OFF_WHH;
    float* sBias = sm + OFF_BIAS;
    float* sB4   = sm + OFF_B4;

    const int tid = threadIdx.x;

    // ---- stage + transpose weights into SMEM (once per CTA) ----
    for (int idx = tid; idx < 20 * 128; idx += NTHREADS) {
        int i = idx >> 7, j = idx & 127;           // sW1t[i*128 + j] = W1[j][i]
        sW1t[idx] = W1[j * 20 + i];
    }
    for (int idx = tid; idx < 64 * 128; idx += NTHREADS) {
        int j = idx >> 6, k = idx & 63;            // sW2t[j*64 + k] = W2[k][j]
        sW2t[idx] = W2[k * 128 + j];
    }
    for (int idx = tid; idx < 64 * 32; idx += NTHREADS) {
        int k = idx >> 5, m = idx & 31;            // sW3t[k*32 + m] = W3[m][k]
        sW3t[idx] = W3[m * 64 + k];
    }
    if (tid < 128) sB1[tid] = b1[tid];
    if (tid < 64)  sB2[tid] = b2[tid];
    if (tid < 32)  { sB3[tid] = b3[tid]; sW4[tid] = W4[tid]; }
    if (tid < 32)  sWih[tid] = W_ih[tid];
    if (tid < 16)  sWhh[tid] = W_hh[tid];
    if (tid < 8)   sBias[tid] = b_ih[tid] + b_hh[tid];
    if (tid == 0)  sB4[0] = b4[0];
    __syncthreads();

    const int stride = gridDim.x * NTHREADS;
    for (int b = blockIdx.x * NTHREADS + tid; b < n; b += stride) {
        // ================= LSTM (scalar fp32) =================
        float h0 = 0.f, h1 = 0.f, c0 = 0.f, c1 = 0.f;
        u64 hb[20];                                  // packed (h,h) broadcasts
        const float* xb = x + (size_t)b * 40;        // [T=10][I=4]
#pragma unroll
        for (int t = 0; t < 10; t++) {
            float4 xt = *reinterpret_cast<const float4*>(xb + t * 4);
            float g[8];
#pragma unroll
            for (int gi = 0; gi < 8; gi++) {
                float a = sBias[gi];
                a = fmaf(xt.x, sWih[gi * 4 + 0], a);
                a = fmaf(xt.y, sWih[gi * 4 + 1], a);
                a = fmaf(xt.z, sWih[gi * 4 + 2], a);
                a = fmaf(xt.w, sWih[gi * 4 + 3], a);
                a = fmaf(h0, sWhh[gi * 2 + 0], a);
                a = fmaf(h1, sWhh[gi * 2 + 1], a);
                g[gi] = a;
            }
            float i0 = sigf(g[0]),      i1 = sigf(g[1]);
            float f0 = sigf(g[2]),      f1 = sigf(g[3]);
            float g0 = tanhfast(g[4]),  g1 = tanhfast(g[5]);
            float o0 = sigf(g[6]),      o1 = sigf(g[7]);
            c0 = fmaf(f0, c0, i0 * g0);
            c1 = fmaf(f1, c1, i1 * g1);
            h0 = o0 * tanhfast(c0);
            h1 = o1 * tanhfast(c1);
            hb[2 * t]     = bcast(h0);
            hb[2 * t + 1] = bcast(h1);
        }

        // ============ MLP layer1(20->128) fused into layer2(128->64) ============
        // acc2: 32 packed pairs of layer-2 accumulators, init with bias
        u64 acc2[32];
#pragma unroll
        for (int k2 = 0; k2 < 32; k2++) acc2[k2] = lds64(&sB2[2 * k2]);

#pragma unroll 4
        for (int jp = 0; jp < 64; jp++) {
            // a1 pair (neurons 2jp, 2jp+1)
            u64 a = lds64(&sB1[2 * jp]);
#pragma unroll
            for (int i = 0; i < 20; i++)
                a = fma2(hb[i], lds64(&sW1t[i * 128 + 2 * jp]), a);
            float a0, a1v;
            unpack2(a, a0, a1v);
            a0  = fmaxf(a0, 0.f);
            a1v = fmaxf(a1v, 0.f);
            u64 v0 = bcast(a0), v1 = bcast(a1v);
            const float* w0 = &sW2t[(2 * jp) * 64];
            const float* w1 = w0 + 64;
#pragma unroll
            for (int k2 = 0; k2 < 32; k2++) {
                acc2[k2] = fma2(v0, lds64(w0 + 2 * k2), acc2[k2]);
                acc2[k2] = fma2(v1, lds64(w1 + 2 * k2), acc2[k2]);
            }
        }

        // ============ layer3 (64->32), incremental from acc2 ============
        u64 acc3[16];
#pragma unroll
        for (int m = 0; m < 16; m++) acc3[m] = lds64(&sB3[2 * m]);
#pragma unroll
        for (int kp = 0; kp < 32; kp++) {
            float s0, s1;
            unpack2(acc2[kp], s0, s1);
            s0 = fmaxf(s0, 0.f);
            s1 = fmaxf(s1, 0.f);
            u64 u0 = bcast(s0), u1 = bcast(s1);
            const float* w0 = &sW3t[(2 * kp) * 32];
            const float* w1 = w0 + 32;
#pragma unroll
            for (int m = 0; m < 16; m++) {
                acc3[m] = fma2(u0, lds64(w0 + 2 * m), acc3[m]);
                acc3[m] = fma2(u1, lds64(w1 + 2 * m), acc3[m]);
            }
        }

        // ============ layer4 (32->1), scalar ============
        float o = sB4[0];
#pragma unroll
        for (int mp = 0; mp < 16; mp++) {
            float t0, t1;
            unpack2(acc3[mp], t0, t1);
            t0 = fmaxf(t0, 0.f);
            t1 = fmaxf(t1, 0.f);
            o = fmaf(t0, sW4[2 * mp], o);
            o = fmaf(t1, sW4[2 * mp + 1], o);
        }
        out[b] = o;
    }
}

extern "C" void kernel_launch(void* const* d_in, const int* in_sizes, int n_in,
                              void* d_out, int out_size)
{
    const float* x    = (const float*)d_in[0];
    const float* W_ih = (const float*)d_in[1];
    const float* W_hh = (const float*)d_in[2];
    const float* b_ih = (const float*)d_in[3];
    const float* b_hh = (const float*)d_in[4];
    const float* W1   = (const float*)d_in[5];
    const float* b1   = (const float*)d_in[6];
    const float* W2   = (const float*)d_in[7];
    const float* b2   = (const float*)d_in[8];
    const float* W3   = (const float*)d_in[9];
    const float* b3   = (const float*)d_in[10];
    const float* W4   = (const float*)d_in[11];
    const float* b4   = (const float*)d_in[12];
    float* out = (float*)d_out;

    static bool attr_set = false;
    if (!attr_set) {
        cudaFuncSetAttribute(lstm_mlp_fused_kernel,
                             cudaFuncAttributeMaxDynamicSharedMemorySize, SMEM_BYTES);
        attr_set = true;
    }

    lstm_mlp_fused_kernel<<<NBLOCKS, NTHREADS, SMEM_BYTES>>>(
        x, W_ih, W_hh, b_ih, b_hh, W1, b1, W2, b2, W3, b3, W4, b4,
        out, out_size);
}